// round 7
// baseline (speedup 1.0000x reference)
#include <cuda_runtime.h>
#include <math.h>

#define NM      64
#define A_DIM   8400
#define E_DIM   128
#define NHEAD   4
#define HDIM    32
#define HWSZ    25600      // 160*160
#define LN_EPS  1e-5f
#define LOG2E   1.4426950408889634f
#define TABN    8192
#define XMIN    -10.0f
#define XMAX    10.0f

#define NB        148            // one block per SM -> always co-resident
#define TPB       512
#define N_POOLB   128            // pool blocks: 3200 float4 each (half a module)
#define NV4       (NM * A_DIM / 4)          // 134400
#define NTHREADS  (NB * TPB)                // 75776

// ---------------- device scratch (no allocation allowed) ----------------
__device__ float        g_partial[N_POOLB];
__device__ float4       g_AB[NHEAD * NM];   // (A1,A2,A3,W); A* pre-scaled log2e*scale
__device__ float        g_qstat[3];         // {Vw, 2*Cwb, Vb+eps} for queries
__device__ float2       g_F2[TABN];         // (F[i], F[i+1]) pairs
__device__ unsigned int g_sync[3];          // {pool_done, tab_done, exit}; zero-init

__device__ __forceinline__ float fast_ex2(float x) {
    float y; asm("ex2.approx.f32 %0, %1;" : "=f"(y) : "f"(x)); return y;
}

__device__ __forceinline__ void spin_until(unsigned int* ctr, unsigned int target) {
    while (*((volatile unsigned int*)ctr) < target) __nanosleep(64);
    __threadfence();   // acquire
}

// full evaluator (cold fallback for |x| > 10)
__device__ __noinline__ float eval_F_cold(float x, float out_b)
{
    float qa = g_qstat[0], qb2 = g_qstat[1], qc = g_qstat[2];
    float r = rsqrtf(fmaf(x, fmaf(qa, x, qb2), qc));
    float acc = out_b;
    #pragma unroll
    for (int h = 0; h < NHEAD; h++) {
        const float4* ABh = g_AB + h * NM;
        float mx = -1e30f;
        #pragma unroll 8
        for (int m = 0; m < NM; m++) {
            float4 ab = ABh[m];
            float s = fmaf(r, fmaf(x, ab.x, ab.y), ab.z);
            mx = fmaxf(mx, s);
        }
        float se = 0.f, ws = 0.f;
        #pragma unroll 8
        for (int m = 0; m < NM; m++) {
            float4 ab = ABh[m];
            float s = fmaf(r, fmaf(x, ab.x, ab.y), ab.z);
            float e = fast_ex2(s - mx);
            se += e;
            ws = fmaf(e, ab.w, ws);
        }
        acc += __fdividef(ws, se);
    }
    return acc;
}

// one head's softmax contribution: ws/se over 64 modules
__device__ __forceinline__ float eval_head(float x, int hh, const float4* __restrict__ sAB,
                                           float qa, float qb2, float qc)
{
    float r = rsqrtf(fmaf(x, fmaf(qa, x, qb2), qc));
    const float4* ABh = sAB + (hh << 6);
    float mx = -1e30f;
    #pragma unroll 8
    for (int m = 0; m < NM; m++) {
        float4 ab = ABh[m];
        float s = fmaf(r, fmaf(x, ab.x, ab.y), ab.z);
        mx = fmaxf(mx, s);
    }
    float se = 0.f, ws = 0.f;
    #pragma unroll 8
    for (int m = 0; m < NM; m++) {
        float4 ab = ABh[m];
        float s = fmaf(r, fmaf(x, ab.x, ab.y), ab.z);
        float e = fast_ex2(s - mx);
        se += e;
        ws = fmaf(e, ab.w, ws);
    }
    return __fdividef(ws, se);
}

// =================== single persistent kernel, 1 block/SM ===================
__global__ __launch_bounds__(TPB) void fused_kernel(
    const float* __restrict__ coeff, const float* __restrict__ proto,
    const float* __restrict__ qw, const float* __restrict__ qb,
    const float* __restrict__ qg, const float* __restrict__ qbeta,
    const float* __restrict__ kw, const float* __restrict__ kb,
    const float* __restrict__ kg, const float* __restrict__ kbeta,
    const float* __restrict__ vw, const float* __restrict__ vb,
    const float* __restrict__ vg, const float* __restrict__ vbeta,
    const float* __restrict__ outw, const float* __restrict__ outb,
    const float* __restrict__ gatew, const float* __restrict__ gateb,
    float* __restrict__ out)
{
    __shared__ float  s_red[16];
    __shared__ float  s_pooled[NM];
    __shared__ float  s_stats[15];
    __shared__ float4 s_k[E_DIM];
    __shared__ float4 s_v[E_DIM];
    __shared__ float4 s_q[E_DIM];
    __shared__ float  s_ow[E_DIM];
    __shared__ float4 sAB[NHEAD * NM];

    const int bid  = blockIdx.x;
    const int t    = threadIdx.x;
    const int gtid = bid * TPB + t;
    const bool isPool = (bid < N_POOLB);
    const bool isTab  = (bid < 64);          // table/coeff blocks (nodes 0..8191)

    // -------- phase 0a: issue pool loads (batched, long-latency) --------
    float4 pv0, pv1, pv2, pv3, pv4, pv5, pv6;
    if (isPool) {
        const float4* p4 = reinterpret_cast<const float4*>(proto) + (size_t)bid * 3200;
        pv0 = p4[t];
        pv1 = p4[t + 512];
        pv2 = p4[t + 1024];
        pv3 = p4[t + 1536];
        pv4 = p4[t + 2048];
        pv5 = p4[t + 2560];
        if (t < 128) pv6 = p4[t + 3072];
        else         pv6 = make_float4(0.f, 0.f, 0.f, 0.f);
    }

    // -------- phase 0b: prefetch apply inputs (overlap with pool DRAM) --------
    const float4* cin = reinterpret_cast<const float4*>(coeff);
    float4* cout = reinterpret_cast<float4*>(out);
    const int slot1 = gtid + NTHREADS;
    const bool s1ok = slot1 < NV4;
    float4 xv0 = cin[gtid];
    float4 xv1 = s1ok ? cin[slot1] : make_float4(0.f, 0.f, 0.f, 0.f);
    float gw0 = __ldg(gatew)     * -LOG2E;
    float gw1 = __ldg(gatew + 1) * -LOG2E;
    float gbv = __ldg(gateb)     * -LOG2E;
    float ob  = __ldg(outb);

    // -------- phase 0c: params + moments (table blocks; overlaps pool) --------
    if (isTab) {
        if (t < E_DIM) {
            s_k[t] = make_float4(kw[t], kb[t], kg[t], kbeta[t]);
            s_v[t] = make_float4(vw[t], vb[t], vg[t], vbeta[t]);
            s_q[t] = make_float4(qw[t], qb[t], qg[t], qbeta[t]);
            s_ow[t] = outw[t];
        }
        if (t >= 64 && t < 96) {
            int lane = t & 31;
            float acc[15];
            #pragma unroll
            for (int i = 0; i < 15; i++) acc[i] = 0.f;
            #pragma unroll
            for (int rep = 0; rep < 4; rep++) {
                int e = lane + rep * 32;
                float a, b;
                a = qw[e]; b = qb[e];
                acc[0] += a; acc[1] += b; acc[2] += a*a; acc[3] += a*b; acc[4] += b*b;
                a = kw[e]; b = kb[e];
                acc[5] += a; acc[6] += b; acc[7] += a*a; acc[8] += a*b; acc[9] += b*b;
                a = vw[e]; b = vb[e];
                acc[10] += a; acc[11] += b; acc[12] += a*a; acc[13] += a*b; acc[14] += b*b;
            }
            #pragma unroll
            for (int off = 16; off; off >>= 1)
                #pragma unroll
                for (int i = 0; i < 15; i++) acc[i] += __shfl_down_sync(0xffffffffu, acc[i], off);
            if (lane == 0) {
                const float inv = 1.0f / (float)E_DIM;
                #pragma unroll
                for (int gi = 0; gi < 3; gi++) {
                    float mw = acc[gi*5+0] * inv;
                    float mb = acc[gi*5+1] * inv;
                    s_stats[gi*5+0] = mw;
                    s_stats[gi*5+1] = mb;
                    s_stats[gi*5+2] = acc[gi*5+2] * inv - mw*mw;
                    s_stats[gi*5+3] = acc[gi*5+3] * inv - mw*mb;
                    s_stats[gi*5+4] = acc[gi*5+4] * inv - mb*mb;
                }
            }
        }
    }

    // -------- phase 1: pool reduce + arrive --------
    if (isPool) {
        float s0 = (pv0.x + pv0.y) + (pv0.z + pv0.w);
        float s1 = (pv1.x + pv1.y) + (pv1.z + pv1.w);
        float s2 = (pv2.x + pv2.y) + (pv2.z + pv2.w);
        float s3 = (pv3.x + pv3.y) + (pv3.z + pv3.w);
        float s4 = (pv4.x + pv4.y) + (pv4.z + pv4.w);
        float s5 = (pv5.x + pv5.y) + (pv5.z + pv5.w);
        float s6 = (pv6.x + pv6.y) + (pv6.z + pv6.w);
        float sum = (((s0 + s1) + (s2 + s3)) + ((s4 + s5) + s6));
        #pragma unroll
        for (int off = 16; off; off >>= 1) sum += __shfl_down_sync(0xffffffffu, sum, off);
        if ((t & 31) == 0) s_red[t >> 5] = sum;
    }
    __syncthreads();
    if (isPool && t == 0) {
        float v = 0.f;
        #pragma unroll
        for (int w2 = 0; w2 < 16; w2++) v += s_red[w2];
        g_partial[bid] = v;
        __threadfence();
        atomicAdd(&g_sync[0], 1u);
    }

    // -------- phase 2: table blocks build coefficients + table --------
    if (isTab) {
        if (t == 0) spin_until(&g_sync[0], N_POOLB);
        __syncthreads();

        if (t < NM)
            s_pooled[t] = (g_partial[2 * t] + g_partial[2 * t + 1]) * (1.0f / (float)HWSZ);
        __syncthreads();

        float qa  = s_stats[2];
        float qb2 = 2.0f * s_stats[3];
        float qc  = s_stats[4] + LN_EPS;
        if (bid == 0 && t == 0) {
            g_qstat[0] = qa; g_qstat[1] = qb2; g_qstat[2] = qc;
        }

        if (t < NHEAD * NM) {
            float mqw = s_stats[0],  mqb = s_stats[1];
            float mkw = s_stats[5],  mkb = s_stats[6];
            float Vkw = s_stats[7],  Ckwb = s_stats[8],  Vkb = s_stats[9];
            float mvw = s_stats[10], mvb = s_stats[11];
            float Vvw = s_stats[12], Cvwb = s_stats[13], Vvb = s_stats[14];
            const float cscale = rsqrtf((float)HDIM) * LOG2E;

            int h = t >> 6, m = t & 63;
            float p = s_pooled[m];
            float rk = rsqrtf(p * p * Vkw + 2.0f * p * Ckwb + Vkb + LN_EPS);
            float rv = rsqrtf(p * p * Vvw + 2.0f * p * Cvwb + Vvb + LN_EPS);

            float a1 = 0.f, a2 = 0.f, a3 = 0.f, w = 0.f;
            #pragma unroll 8
            for (int j = 0; j < HDIM; j++) {
                int e = h * HDIM + j;
                float4 kk = s_k[e];
                float4 vv = s_v[e];
                float4 qq = s_q[e];
                float ke = ((kk.x - mkw) * p + (kk.y - mkb)) * rk * kk.z + kk.w;
                float ve = ((vv.x - mvw) * p + (vv.y - mvb)) * rv * vv.z + vv.w;
                float uq = (qq.x - mqw) * qq.z;
                float tq = (qq.y - mqb) * qq.z;
                a1 = fmaf(uq, ke, a1);
                a2 = fmaf(tq, ke, a2);
                a3 = fmaf(qq.w, ke, a3);
                w  = fmaf(ve, s_ow[e], w);
            }
            float4 out4 = make_float4(a1 * cscale, a2 * cscale, a3 * cscale, w);
            sAB[t] = out4;
            if (bid == 0) g_AB[t] = out4;
        }
        __syncthreads();

        // table: 4 threads per node, one head each; heads are independent terms
        const float hstep = (XMAX - XMIN) / (float)(TABN - 1);
        int node = gtid >> 2;                 // bid<64 -> node in [0, 8192)
        int hh   = t & 3;
        float x  = XMIN + (float)node * hstep;
        float part = eval_head(x, hh, sAB, qa, qb2, qc);
        part += __shfl_xor_sync(0xffffffffu, part, 1);
        part += __shfl_xor_sync(0xffffffffu, part, 2);
        if (hh == 0) {
            float F = part + ob;
            g_F2[node].x = F;
            if (node > 0) g_F2[node - 1].y = F;
        }
        __threadfence();
    }
    __syncthreads();
    if (t == 0) atomicAdd(&g_sync[1], 1u);

    // -------- phase 3: apply (inputs already in registers) --------
    if (t == 0) spin_until(&g_sync[1], NB);
    __syncthreads();

    const float INVH = (float)(TABN - 1) / (XMAX - XMIN);
    const float BIAS = -XMIN * INVH;

    float xin[8] = {xv0.x, xv0.y, xv0.z, xv0.w, xv1.x, xv1.y, xv1.z, xv1.w};
    float2 p[8];
    float fpos[8];
    bool inr[8];
    #pragma unroll
    for (int j = 0; j < 8; j++) {
        float x = xin[j];
        inr[j] = (x >= XMIN) && (x <= XMAX);
        float tpos = fmaf(x, INVH, BIAS);
        int q0 = __float2int_rd(tpos);
        q0 = (q0 < 0) ? 0 : ((q0 > TABN - 2) ? TABN - 2 : q0);
        fpos[j] = tpos - (float)q0;
        p[j] = g_F2[q0];
    }

    float res[8];
    #pragma unroll
    for (int j = 0; j < 8; j++) {
        float x = xin[j];
        float F = inr[j] ? fmaf(fpos[j], p[j].y - p[j].x, p[j].x)
                         : eval_F_cold(x, ob);
        float z = fmaf(gw1, F, fmaf(gw0, x, gbv));
        float g = __fdividef(1.0f, 1.0f + fast_ex2(z));
        res[j] = fmaf(g, F - x, x);
    }
    cout[gtid] = make_float4(res[0], res[1], res[2], res[3]);
    if (s1ok) cout[slot1] = make_float4(res[4], res[5], res[6], res[7]);

    // -------- epilogue: last block resets counters for next replay --------
    __syncthreads();
    if (t == 0) {
        unsigned int old = atomicAdd(&g_sync[2], 1u);
        if (old == (unsigned int)(NB - 1)) {
            atomicExch(&g_sync[0], 0u);
            atomicExch(&g_sync[1], 0u);
            atomicExch(&g_sync[2], 0u);
        }
    }
}

// ---------------- launch ----------------
extern "C" void kernel_launch(void* const* d_in, const int* in_sizes, int n_in,
                              void* d_out, int out_size) {
    (void)in_sizes; (void)n_in; (void)out_size;
    const float* coeff = (const float*)d_in[0];
    const float* proto = (const float*)d_in[1];
    const float* qw    = (const float*)d_in[2];
    const float* qb    = (const float*)d_in[3];
    const float* qg    = (const float*)d_in[4];
    const float* qbeta = (const float*)d_in[5];
    const float* kw    = (const float*)d_in[6];
    const float* kb    = (const float*)d_in[7];
    const float* kg    = (const float*)d_in[8];
    const float* kbeta = (const float*)d_in[9];
    const float* vw    = (const float*)d_in[10];
    const float* vb    = (const float*)d_in[11];
    const float* vg    = (const float*)d_in[12];
    const float* vbeta = (const float*)d_in[13];
    const float* outw  = (const float*)d_in[14];
    const float* outb  = (const float*)d_in[15];
    const float* gatew = (const float*)d_in[16];
    const float* gateb = (const float*)d_in[17];
    float* out = (float*)d_out;

    fused_kernel<<<NB, TPB>>>(coeff, proto,
                              qw, qb, qg, qbeta, kw, kb, kg, kbeta,
                              vw, vb, vg, vbeta, outw, outb,
                              gatew, gateb, out);
}

// round 8
// speedup vs baseline: 1.6277x; 1.6277x over previous
#include <cuda_runtime.h>
#include <math.h>

#define NM      64
#define A_DIM   8400
#define E_DIM   128
#define NHEAD   4
#define HDIM    32
#define HWSZ    25600      // 160*160
#define LN_EPS  1e-5f
#define LOG2E   1.4426950408889634f
#define TABN    8192
#define XMIN    -10.0f
#define XMAX    10.0f

#define N_POOLB   320            // pool blocks: 1280 float4 each (5 per module, exact)
#define N_TABB    64             // table blocks: 128 nodes each (2 threads/node)
#define GRID_A    (N_POOLB + N_TABB)   // 384 blocks, one wave
#define TPB       256

#define APPLY_BLOCKS 350
#define APPLY_TPB    384         // 350*384 = 134400 float4 exactly

// ---------------- device scratch (no allocation allowed) ----------------
__device__ float        g_partial[N_POOLB];
__device__ float4       g_AB[NHEAD * NM];   // (A1,A2,A3,W); A* pre-scaled log2e*scale
__device__ float        g_qstat[3];         // {Vw, 2*Cwb, Vb+eps} for queries
__device__ float2       g_F2[TABN];         // (F[i], F[i+1]) pairs
__device__ unsigned int g_sync[2];          // {pool_done, tab_done}; zero-init

__device__ __forceinline__ float fast_ex2(float x) {
    float y; asm("ex2.approx.f32 %0, %1;" : "=f"(y) : "f"(x)); return y;
}

__device__ __forceinline__ void spin_until(unsigned int* ctr, unsigned int target) {
    while (*((volatile unsigned int*)ctr) < target) __nanosleep(64);
    __threadfence();   // acquire
}

// one head's softmax contribution: ws/se over 64 modules (r precomputed)
__device__ __forceinline__ float eval_head(float x, float r, const float4* __restrict__ ABh)
{
    float mx = -1e30f;
    #pragma unroll 8
    for (int m = 0; m < NM; m++) {
        float4 ab = ABh[m];
        float s = fmaf(r, fmaf(x, ab.x, ab.y), ab.z);
        mx = fmaxf(mx, s);
    }
    float se = 0.f, ws = 0.f;
    #pragma unroll 8
    for (int m = 0; m < NM; m++) {
        float4 ab = ABh[m];
        float s = fmaf(r, fmaf(x, ab.x, ab.y), ab.z);
        float e = fast_ex2(s - mx);
        se += e;
        ws = fmaf(e, ab.w, ws);
    }
    return __fdividef(ws, se);
}

// full evaluator (cold fallback for |x| > 10, from global coeffs)
__device__ __noinline__ float eval_F_cold(float x, float out_b)
{
    float qa = g_qstat[0], qb2 = g_qstat[1], qc = g_qstat[2];
    float r = rsqrtf(fmaf(x, fmaf(qa, x, qb2), qc));
    float acc = out_b;
    #pragma unroll
    for (int h = 0; h < NHEAD; h++)
        acc += eval_head(x, r, g_AB + h * NM);
    return acc;
}

// =================== kernel A: pool + table (one wave) ===================
__global__ __launch_bounds__(TPB) void pooltab_kernel(
    const float* __restrict__ proto,
    const float* __restrict__ qw, const float* __restrict__ qb,
    const float* __restrict__ qg, const float* __restrict__ qbeta,
    const float* __restrict__ kw, const float* __restrict__ kb,
    const float* __restrict__ kg, const float* __restrict__ kbeta,
    const float* __restrict__ vw, const float* __restrict__ vb,
    const float* __restrict__ vg, const float* __restrict__ vbeta,
    const float* __restrict__ outw, const float* __restrict__ outb)
{
    const int bid = blockIdx.x;
    const int t   = threadIdx.x;

    // ======================= POOL role =======================
    if (bid < N_POOLB) {
        __shared__ float s_red[8];
        const float4* p4 = reinterpret_cast<const float4*>(proto) + (size_t)bid * 1280;
        float4 v0 = p4[t];
        float4 v1 = p4[t + 256];
        float4 v2 = p4[t + 512];
        float4 v3 = p4[t + 768];
        float4 v4 = p4[t + 1024];
        float s0 = (v0.x + v0.y) + (v0.z + v0.w);
        float s1 = (v1.x + v1.y) + (v1.z + v1.w);
        float s2 = (v2.x + v2.y) + (v2.z + v2.w);
        float s3 = (v3.x + v3.y) + (v3.z + v3.w);
        float s4 = (v4.x + v4.y) + (v4.z + v4.w);
        float sum = ((s0 + s1) + (s2 + s3)) + s4;
        #pragma unroll
        for (int off = 16; off; off >>= 1) sum += __shfl_down_sync(0xffffffffu, sum, off);
        if ((t & 31) == 0) s_red[t >> 5] = sum;
        __syncthreads();
        if (t == 0) {
            float v = 0.f;
            #pragma unroll
            for (int w2 = 0; w2 < 8; w2++) v += s_red[w2];
            g_partial[bid] = v;
            __threadfence();   // release
            atomicAdd(&g_sync[0], 1u);
        }
        return;
    }

    // ======================= TABLE role =======================
    {
        const int tb = bid - N_POOLB;        // 0..63
        __shared__ float  s_pooled[NM];
        __shared__ float  s_stats[15];
        __shared__ float4 s_k[E_DIM];
        __shared__ float4 s_v[E_DIM];
        __shared__ float4 s_q[E_DIM];
        __shared__ float  s_ow[E_DIM];
        __shared__ float4 sAB[NHEAD * NM];

        // phase A (overlaps pool): stage params + moments
        if (t < E_DIM) {
            s_k[t] = make_float4(kw[t], kb[t], kg[t], kbeta[t]);
            s_v[t] = make_float4(vw[t], vb[t], vg[t], vbeta[t]);
            s_q[t] = make_float4(qw[t], qb[t], qg[t], qbeta[t]);
            s_ow[t] = outw[t];
        }
        if (t >= 64 && t < 96) {
            int lane = t & 31;
            float acc[15];
            #pragma unroll
            for (int i = 0; i < 15; i++) acc[i] = 0.f;
            #pragma unroll
            for (int rep = 0; rep < 4; rep++) {
                int e = lane + rep * 32;
                float a, b;
                a = qw[e]; b = qb[e];
                acc[0] += a; acc[1] += b; acc[2] += a*a; acc[3] += a*b; acc[4] += b*b;
                a = kw[e]; b = kb[e];
                acc[5] += a; acc[6] += b; acc[7] += a*a; acc[8] += a*b; acc[9] += b*b;
                a = vw[e]; b = vb[e];
                acc[10] += a; acc[11] += b; acc[12] += a*a; acc[13] += a*b; acc[14] += b*b;
            }
            #pragma unroll
            for (int off = 16; off; off >>= 1)
                #pragma unroll
                for (int i = 0; i < 15; i++) acc[i] += __shfl_down_sync(0xffffffffu, acc[i], off);
            if (lane == 0) {
                const float inv = 1.0f / (float)E_DIM;
                #pragma unroll
                for (int gi = 0; gi < 3; gi++) {
                    float mw = acc[gi*5+0] * inv;
                    float mb = acc[gi*5+1] * inv;
                    s_stats[gi*5+0] = mw;
                    s_stats[gi*5+1] = mb;
                    s_stats[gi*5+2] = acc[gi*5+2] * inv - mw*mw;
                    s_stats[gi*5+3] = acc[gi*5+3] * inv - mw*mb;
                    s_stats[gi*5+4] = acc[gi*5+4] * inv - mb*mb;
                }
            }
        }

        // wait for pool
        if (t == 0) spin_until(&g_sync[0], N_POOLB);
        __syncthreads();

        if (t < NM) {
            float s = 0.f;
            #pragma unroll
            for (int j = 0; j < 5; j++) s += g_partial[t * 5 + j];
            s_pooled[t] = s * (1.0f / (float)HWSZ);
        }
        __syncthreads();

        float qa  = s_stats[2];
        float qb2 = 2.0f * s_stats[3];
        float qc  = s_stats[4] + LN_EPS;
        if (tb == 0 && t == 0) {
            g_qstat[0] = qa; g_qstat[1] = qb2; g_qstat[2] = qc;
        }

        // coefficients: thread t -> (head, module) entry t (256 entries exactly)
        {
            float mqw = s_stats[0],  mqb = s_stats[1];
            float mkw = s_stats[5],  mkb = s_stats[6];
            float Vkw = s_stats[7],  Ckwb = s_stats[8],  Vkb = s_stats[9];
            float mvw = s_stats[10], mvb = s_stats[11];
            float Vvw = s_stats[12], Cvwb = s_stats[13], Vvb = s_stats[14];
            const float cscale = rsqrtf((float)HDIM) * LOG2E;

            int h = t >> 6, m = t & 63;
            float p = s_pooled[m];
            float rk = rsqrtf(p * p * Vkw + 2.0f * p * Ckwb + Vkb + LN_EPS);
            float rv = rsqrtf(p * p * Vvw + 2.0f * p * Cvwb + Vvb + LN_EPS);

            float a1 = 0.f, a2 = 0.f, a3 = 0.f, w = 0.f;
            #pragma unroll 8
            for (int j = 0; j < HDIM; j++) {
                int e = h * HDIM + j;
                float4 kk = s_k[e];
                float4 vv = s_v[e];
                float4 qq = s_q[e];
                float ke = ((kk.x - mkw) * p + (kk.y - mkb)) * rk * kk.z + kk.w;
                float ve = ((vv.x - mvw) * p + (vv.y - mvb)) * rv * vv.z + vv.w;
                float uq = (qq.x - mqw) * qq.z;
                float tq = (qq.y - mqb) * qq.z;
                a1 = fmaf(uq, ke, a1);
                a2 = fmaf(tq, ke, a2);
                a3 = fmaf(qq.w, ke, a3);
                w  = fmaf(ve, s_ow[e], w);
            }
            float4 out4 = make_float4(a1 * cscale, a2 * cscale, a3 * cscale, w);
            sAB[t] = out4;
            if (tb == 0) g_AB[t] = out4;
        }
        __syncthreads();

        // table: 2 threads per node (2 heads each), shfl-combine
        const float hstep = (XMAX - XMIN) / (float)(TABN - 1);
        float ob = outb[0];
        int node = tb * 128 + (t >> 1);
        int hp   = (t & 1) * 2;              // heads {0,1} or {2,3}
        float x  = XMIN + (float)node * hstep;
        float r  = rsqrtf(fmaf(x, fmaf(qa, x, qb2), qc));
        float part = eval_head(x, r, sAB + (hp << 6))
                   + eval_head(x, r, sAB + ((hp + 1) << 6));
        part += __shfl_xor_sync(0xffffffffu, part, 1);
        if ((t & 1) == 0) {
            float F = part + ob;
            g_F2[node].x = F;
            if (node > 0) g_F2[node - 1].y = F;
        }
        __threadfence();
        __syncthreads();
        // last tab block resets counters (all tab blocks have passed the spin)
        if (t == 0) {
            unsigned int old = atomicAdd(&g_sync[1], 1u);
            if (old == (unsigned int)(N_TABB - 1)) {
                atomicExch(&g_sync[0], 0u);
                atomicExch(&g_sync[1], 0u);
            }
        }
    }
}

// =================== kernel B: pointwise apply ===================
__global__ __launch_bounds__(APPLY_TPB) void apply_kernel(
    const float* __restrict__ coeff, float* __restrict__ out,
    const float* __restrict__ gatew, const float* __restrict__ gateb,
    const float* __restrict__ outb)
{
    int tid = blockIdx.x * APPLY_TPB + threadIdx.x;   // one float4 each
    const float4* cin = reinterpret_cast<const float4*>(coeff);
    float4* cout = reinterpret_cast<float4*>(out);
    float gw0 = __ldg(gatew)     * -LOG2E;
    float gw1 = __ldg(gatew + 1) * -LOG2E;
    float gbv = __ldg(gateb)     * -LOG2E;

    const float INVH = (float)(TABN - 1) / (XMAX - XMIN);
    const float BIAS = -XMIN * INVH;

    float4 xv = cin[tid];
    float xin[4] = {xv.x, xv.y, xv.z, xv.w};

    float2 p[4];
    float fpos[4];
    bool inr[4];
    #pragma unroll
    for (int j = 0; j < 4; j++) {
        float x = xin[j];
        inr[j] = (x >= XMIN) && (x <= XMAX);
        float tpos = fmaf(x, INVH, BIAS);
        int q0 = __float2int_rd(tpos);
        q0 = (q0 < 0) ? 0 : ((q0 > TABN - 2) ? TABN - 2 : q0);
        fpos[j] = tpos - (float)q0;
        p[j] = g_F2[q0];
    }

    float res[4];
    #pragma unroll
    for (int j = 0; j < 4; j++) {
        float x = xin[j];
        float F = inr[j] ? fmaf(fpos[j], p[j].y - p[j].x, p[j].x)
                         : eval_F_cold(x, __ldg(outb));
        float z = fmaf(gw1, F, fmaf(gw0, x, gbv));
        float g = __fdividef(1.0f, 1.0f + fast_ex2(z));
        res[j] = fmaf(g, F - x, x);
    }
    cout[tid] = make_float4(res[0], res[1], res[2], res[3]);
}

// ---------------- launch ----------------
extern "C" void kernel_launch(void* const* d_in, const int* in_sizes, int n_in,
                              void* d_out, int out_size) {
    (void)in_sizes; (void)n_in; (void)out_size;
    const float* coeff = (const float*)d_in[0];
    const float* proto = (const float*)d_in[1];
    const float* qw    = (const float*)d_in[2];
    const float* qb    = (const float*)d_in[3];
    const float* qg    = (const float*)d_in[4];
    const float* qbeta = (const float*)d_in[5];
    const float* kw    = (const float*)d_in[6];
    const float* kb    = (const float*)d_in[7];
    const float* kg    = (const float*)d_in[8];
    const float* kbeta = (const float*)d_in[9];
    const float* vw    = (const float*)d_in[10];
    const float* vb    = (const float*)d_in[11];
    const float* vg    = (const float*)d_in[12];
    const float* vbeta = (const float*)d_in[13];
    const float* outw  = (const float*)d_in[14];
    const float* outb  = (const float*)d_in[15];
    const float* gatew = (const float*)d_in[16];
    const float* gateb = (const float*)d_in[17];
    float* out = (float*)d_out;

    pooltab_kernel<<<GRID_A, TPB>>>(proto,
                                    qw, qb, qg, qbeta, kw, kb, kg, kbeta,
                                    vw, vb, vg, vbeta, outw, outb);
    apply_kernel<<<APPLY_BLOCKS, APPLY_TPB>>>(coeff, out, gatew, gateb, outb);
}